// round 11
// baseline (speedup 1.0000x reference)
#include <cuda_runtime.h>
#include <cstdint>

// ---------------------------------------------------------------------------
// LNSNet: conv1(1->32,3x3)+relu+pool2 -> conv2(32->64,3x3)+relu+pool2 (mma tf32)
//         -> fc1(9216->128, mma tf32, split-K)+relu -> fc2(128->10).  Batch 512.
// ---------------------------------------------------------------------------

__device__ float g_p1[512 * 32 * 26 * 26];     // pool1 output
__device__ float g_p2[512 * 64 * 12 * 12];     // pool2 output (fc1 input)
__device__ float g_part[36 * 512 * 128];       // fc1 split-K partials
__device__ float g_h[512 * 128];               // fc1 relu output

__device__ __forceinline__ float tf32_rna(float v) {
    uint32_t u;
    asm("cvt.rna.tf32.f32 %0, %1;" : "=r"(u) : "f"(v));
    return __uint_as_float(u);
}

// m16n8k8 tf32 mma, row.col, fp32 accumulate (sm_80+ baseline PTX)
__device__ __forceinline__ void mma_tf32(float* c,
                                         float a0, float a1, float a2, float a3,
                                         float b0, float b1)
{
    asm volatile(
        "mma.sync.aligned.m16n8k8.row.col.f32.tf32.tf32.f32 "
        "{%0,%1,%2,%3}, {%4,%5,%6,%7}, {%8,%9}, {%0,%1,%2,%3};"
        : "+f"(c[0]), "+f"(c[1]), "+f"(c[2]), "+f"(c[3])
        : "r"(__float_as_uint(a0)), "r"(__float_as_uint(a1)),
          "r"(__float_as_uint(a2)), "r"(__float_as_uint(a3)),
          "r"(__float_as_uint(b0)), "r"(__float_as_uint(b1)));
}

// ---------------------------------------------------------------------------
// Kernel 1: conv1 + ReLU + maxpool (fp32, weight-resident oc-chunks)
// Per pooled pos: 16 LDS reused across an 8-oc chunk (288 FMA)  -> FFMA-bound.
// ---------------------------------------------------------------------------
__global__ void __launch_bounds__(256) k_conv1(const float* __restrict__ x,
                                               const float* __restrict__ w,
                                               const float* __restrict__ bias)
{
    __shared__ float s_x[54 * 55];
    __shared__ float s_w[32 * 9];
    __shared__ float s_b[32];

    const int bb = blockIdx.x;
    const float* xb = x + bb * 54 * 54;
    for (int i = threadIdx.x; i < 54 * 54; i += 256) {
        int y = i / 54, c = i - y * 54;
        s_x[y * 55 + c] = xb[i];
    }
    for (int i = threadIdx.x; i < 32 * 9; i += 256) s_w[i] = w[i];
    if (threadIdx.x < 32) s_b[threadIdx.x] = bias[threadIdx.x];
    __syncthreads();

    float* outb = g_p1 + bb * 32 * 676;
#pragma unroll 1
    for (int ch = 0; ch < 4; ch++) {
        float wr[8][9];
        float bv[8];
#pragma unroll
        for (int j = 0; j < 8; j++) {
            bv[j] = s_b[ch * 8 + j];
#pragma unroll
            for (int i = 0; i < 9; i++) wr[j][i] = s_w[(ch * 8 + j) * 9 + i];
        }
        for (int pos = threadIdx.x; pos < 676; pos += 256) {
            const int py = pos / 26, px = pos - py * 26;
            const int Y0 = py * 2, X0 = px * 2;
            float in[4][4];
#pragma unroll
            for (int dy = 0; dy < 4; dy++)
#pragma unroll
                for (int dx = 0; dx < 4; dx++)
                    in[dy][dx] = s_x[(Y0 + dy) * 55 + X0 + dx];
#pragma unroll
            for (int j = 0; j < 8; j++) {
                float m = 0.0f;
#pragma unroll
                for (int dy = 0; dy < 2; dy++)
#pragma unroll
                    for (int dx = 0; dx < 2; dx++) {
                        float acc = bv[j];
#pragma unroll
                        for (int ky = 0; ky < 3; ky++)
#pragma unroll
                            for (int kx = 0; kx < 3; kx++)
                                acc = fmaf(wr[j][ky * 3 + kx],
                                           in[dy + ky][dx + kx], acc);
                        m = fmaxf(m, acc);
                    }
                outb[(ch * 8 + j) * 676 + pos] = m;
            }
        }
    }
}

// ---------------------------------------------------------------------------
// Kernel 2: conv2 via mma.sync tf32 implicit-im2col + ReLU + maxpool.
// (unchanged from R9 — passed at rel_err 2.6e-4)
// ---------------------------------------------------------------------------
#define C2_XS     21632
#define C2_BS     20736
#define C2_SMEMF  (C2_XS + C2_BS + 288)          // 42656 floats
#define C2_DSMEM  (C2_SMEMF * 4)                 // 170624 bytes

__global__ void __launch_bounds__(288, 1) k_conv2(const float* __restrict__ w,
                                                  const float* __restrict__ bias)
{
    extern __shared__ float sm[];
    float* Xs  = sm;                 // 32 planes of 26x26
    float* Bsm = sm + C2_XS;         // [288][72]
    int*   offs = (int*)(sm + C2_XS + C2_BS);    // [288]
    __shared__ float s_b[64];

    const int tid = threadIdx.x;
    const int wid = tid >> 5, lane = tid & 31;
    const int grp = lane >> 2, qid = lane & 3;
    const int bb = blockIdx.x;

    if (tid < 288) {
        const int ic = tid / 9, r = tid - ic * 9;
        offs[tid] = ic * 676 + (r / 3) * 26 + (r % 3);
    }
    if (tid < 64) s_b[tid] = bias[tid];

    if (wid < 2) {
        const int oc = wid * 32 + lane;
        const float* wr = w + oc * 288;
#pragma unroll 4
        for (int k = 0; k < 288; k += 4) {
            const float4 v = *(const float4*)(wr + k);
            Bsm[(k + 0) * 72 + oc] = tf32_rna(v.x);
            Bsm[(k + 1) * 72 + oc] = tf32_rna(v.y);
            Bsm[(k + 2) * 72 + oc] = tf32_rna(v.z);
            Bsm[(k + 3) * 72 + oc] = tf32_rna(v.w);
        }
    } else {
        const float* src = g_p1 + bb * C2_XS;
        for (int i = tid - 64; i < C2_XS; i += 224)
            Xs[i] = tf32_rna(src[i]);
    }
    __syncthreads();

    int poA[4], poB[4];
#pragma unroll
    for (int mt = 0; mt < 4; mt++) {
        const int rA = (wid * 4 + mt) * 16 + grp;
        const int yA = rA / 24, xA = rA - yA * 24;
        poA[mt] = yA * 26 + xA;
        const int rB = rA + 8;
        const int yB = rB / 24, xB = rB - yB * 24;
        poB[mt] = yB * 26 + xB;
    }

    float c[4][8][4];
#pragma unroll
    for (int mt = 0; mt < 4; mt++)
#pragma unroll
        for (int nt = 0; nt < 8; nt++)
#pragma unroll
            for (int j = 0; j < 4; j++) c[mt][nt][j] = 0.0f;

    for (int ks = 0; ks < 36; ks++) {
        const int klo = ks * 8 + qid;
        const int offlo = offs[klo];
        const int offhi = offs[klo + 4];

        const float* bl = Bsm + klo * 72 + grp;
        float bq[8][2];
#pragma unroll
        for (int nt = 0; nt < 8; nt++) {
            bq[nt][0] = bl[nt * 8];
            bq[nt][1] = bl[4 * 72 + nt * 8];
        }

#pragma unroll
        for (int mt = 0; mt < 4; mt++) {
            const float a0 = Xs[offlo + poA[mt]];
            const float a1 = Xs[offlo + poB[mt]];
            const float a2 = Xs[offhi + poA[mt]];
            const float a3 = Xs[offhi + poB[mt]];
#pragma unroll
            for (int nt = 0; nt < 8; nt++)
                mma_tf32(c[mt][nt], a0, a1, a2, a3, bq[nt][0], bq[nt][1]);
        }
    }

    __syncthreads();

    float* cb = sm;    // [576][66]
#pragma unroll
    for (int mt = 0; mt < 4; mt++) {
        const int row = (wid * 4 + mt) * 16 + grp;
#pragma unroll
        for (int nt = 0; nt < 8; nt++) {
            const int col = nt * 8 + qid * 2;
            const float b0 = s_b[col], b1 = s_b[col + 1];
            cb[row * 66 + col]           = fmaxf(c[mt][nt][0] + b0, 0.0f);
            cb[row * 66 + col + 1]       = fmaxf(c[mt][nt][1] + b1, 0.0f);
            cb[(row + 8) * 66 + col]     = fmaxf(c[mt][nt][2] + b0, 0.0f);
            cb[(row + 8) * 66 + col + 1] = fmaxf(c[mt][nt][3] + b1, 0.0f);
        }
    }
    __syncthreads();

    float* outb = g_p2 + bb * 9216;
    for (int i = tid; i < 9216; i += 288) {
        const int oc = i / 144, r = i - oc * 144;
        const int py = r / 12, px = r - py * 12;
        const int p0 = (2 * py) * 24 + 2 * px;
        const float v0 = cb[p0 * 66 + oc];
        const float v1 = cb[(p0 + 1) * 66 + oc];
        const float v2 = cb[(p0 + 24) * 66 + oc];
        const float v3 = cb[(p0 + 25) * 66 + oc];
        outb[i] = fmaxf(fmaxf(v0, v1), fmaxf(v2, v3));
    }
}

// ---------------------------------------------------------------------------
// Kernel 3: fc1 via mma.sync tf32, split-K.
// Grid (4 m-tiles of 128, 36 k-splits of 256) = 144 CTAs (~1 wave).
// smem: As[128][68], Bs[128][68] (stride 68 -> bank 4*grp+qid, conflict-free).
// 8 warps: warp tile 32m x 64n (2 m-tiles x 8 n-tiles).
// ---------------------------------------------------------------------------
#define F1_ST     68
#define F1_SMEMF  (2 * 128 * F1_ST)      // 17408 floats
#define F1_DSMEM  (F1_SMEMF * 4)         // 69632 bytes

__global__ void __launch_bounds__(256, 1) k_fc1(const float* __restrict__ W)
{
    extern __shared__ float fsm[];
    float* As = fsm;                     // [128][68]  rows = m
    float* Bs = fsm + 128 * F1_ST;       // [128][68]  rows = n

    const int mb = blockIdx.x;           // 0..3
    const int sp = blockIdx.y;           // 0..35
    const int tid = threadIdx.x;
    const int wid = tid >> 5, lane = tid & 31;
    const int grp = lane >> 2, qid = lane & 3;
    const int wm = (wid & 3) * 32, wn = (wid >> 2) * 64;
    const int m0 = mb * 128, k0 = sp * 256;

    float c[2][8][4];
#pragma unroll
    for (int mt = 0; mt < 2; mt++)
#pragma unroll
        for (int nt = 0; nt < 8; nt++)
#pragma unroll
            for (int j = 0; j < 4; j++) c[mt][nt][j] = 0.0f;

#pragma unroll 1
    for (int kc = 0; kc < 256; kc += 64) {
        __syncthreads();   // previous chunk's reads done before overwrite
#pragma unroll
        for (int i = tid; i < 2048; i += 256) {
            const int row = i >> 4, c4 = (i & 15) * 4;
            const float4 v = *(const float4*)(g_p2 + (m0 + row) * 9216 + k0 + kc + c4);
            float* d = As + row * F1_ST + c4;
            d[0] = tf32_rna(v.x); d[1] = tf32_rna(v.y);
            d[2] = tf32_rna(v.z); d[3] = tf32_rna(v.w);
        }
#pragma unroll
        for (int i = tid; i < 2048; i += 256) {
            const int n = i >> 4, c4 = (i & 15) * 4;
            const float4 v = *(const float4*)(W + n * 9216 + k0 + kc + c4);
            float* d = Bs + n * F1_ST + c4;
            d[0] = tf32_rna(v.x); d[1] = tf32_rna(v.y);
            d[2] = tf32_rna(v.z); d[3] = tf32_rna(v.w);
        }
        __syncthreads();

#pragma unroll
        for (int ks = 0; ks < 8; ks++) {
            const int k8 = ks * 8;
            float bq[8][2];
            const float* bl = Bs + (wn + grp) * F1_ST + k8 + qid;
#pragma unroll
            for (int nt = 0; nt < 8; nt++) {
                bq[nt][0] = bl[nt * 8 * F1_ST];
                bq[nt][1] = bl[nt * 8 * F1_ST + 4];
            }
#pragma unroll
            for (int mt = 0; mt < 2; mt++) {
                const float* al = As + (wm + mt * 16 + grp) * F1_ST + k8 + qid;
                const float a0 = al[0];
                const float a1 = al[8 * F1_ST];
                const float a2 = al[4];
                const float a3 = al[8 * F1_ST + 4];
#pragma unroll
                for (int nt = 0; nt < 8; nt++)
                    mma_tf32(c[mt][nt], a0, a1, a2, a3, bq[nt][0], bq[nt][1]);
            }
        }
    }

    // write disjoint partial slice
    float* out = g_part + sp * 65536 + m0 * 128;
#pragma unroll
    for (int mt = 0; mt < 2; mt++) {
        const int row = wm + mt * 16 + grp;
#pragma unroll
        for (int nt = 0; nt < 8; nt++) {
            const int col = wn + nt * 8 + qid * 2;
            out[row * 128 + col]           = c[mt][nt][0];
            out[row * 128 + col + 1]       = c[mt][nt][1];
            out[(row + 8) * 128 + col]     = c[mt][nt][2];
            out[(row + 8) * 128 + col + 1] = c[mt][nt][3];
        }
    }
}

// ---------------------------------------------------------------------------
// Kernel 4: reduce split-K partials + bias + ReLU
// ---------------------------------------------------------------------------
__global__ void k_fc1red(const float* __restrict__ b1)
{
    const int idx = blockIdx.x * blockDim.x + threadIdx.x;
    const int n = idx & 127;
    float s = b1[n];
#pragma unroll
    for (int sp = 0; sp < 36; sp++) s += g_part[sp * 65536 + idx];
    g_h[idx] = fmaxf(s, 0.0f);
}

// ---------------------------------------------------------------------------
// Kernel 5: fc2 (128 -> 10)
// ---------------------------------------------------------------------------
__global__ void __launch_bounds__(128) k_fc2(const float* __restrict__ W2,
                                             const float* __restrict__ b2,
                                             float* __restrict__ out)
{
    __shared__ float sh[128];
    const int bb = blockIdx.x;
    const int tid = threadIdx.x;
    sh[tid] = g_h[bb * 128 + tid];
    __syncthreads();
    const int warp = tid >> 5, lane = tid & 31;
    for (int o = warp; o < 10; o += 4) {
        float s = 0.0f;
#pragma unroll
        for (int i = 0; i < 4; i++)
            s = fmaf(sh[lane + 32 * i], W2[o * 128 + lane + 32 * i], s);
#pragma unroll
        for (int off = 16; off > 0; off >>= 1)
            s += __shfl_down_sync(0xffffffffu, s, off);
        if (lane == 0) out[bb * 10 + o] = s + b2[o];
    }
}

// ---------------------------------------------------------------------------
extern "C" void kernel_launch(void* const* d_in, const int* in_sizes, int n_in,
                              void* d_out, int out_size)
{
    const float* x   = (const float*)d_in[0];
    const float* c1w = (const float*)d_in[1];
    const float* c1b = (const float*)d_in[2];
    const float* c2w = (const float*)d_in[3];
    const float* c2b = (const float*)d_in[4];
    const float* f1w = (const float*)d_in[5];
    const float* f1b = (const float*)d_in[6];
    const float* f2w = (const float*)d_in[7];
    const float* f2b = (const float*)d_in[8];
    float* out = (float*)d_out;

    cudaFuncSetAttribute(k_conv2, cudaFuncAttributeMaxDynamicSharedMemorySize,
                         C2_DSMEM);
    cudaFuncSetAttribute(k_fc1, cudaFuncAttributeMaxDynamicSharedMemorySize,
                         F1_DSMEM);

    k_conv1<<<512, 256>>>(x, c1w, c1b);
    k_conv2<<<512, 288, C2_DSMEM>>>(c2w, c2b);
    dim3 g3(4, 36);
    k_fc1<<<g3, 256, F1_DSMEM>>>(f1w);
    k_fc1red<<<256, 256>>>(f1b);
    k_fc2<<<512, 128>>>(f2w, f2b, out);
}

// round 15
// speedup vs baseline: 1.0920x; 1.0920x over previous
#include <cuda_runtime.h>
#include <cstdint>

// ---------------------------------------------------------------------------
// LNSNet: conv1(1->32,3x3)+relu+pool2 -> conv2(32->64,3x3)+relu+pool2 (mma tf32)
//         -> fc1(9216->128)+relu -> fc2(128->10).  Batch 512.
// ---------------------------------------------------------------------------

__device__ float g_p1[512 * 32 * 26 * 26];     // pool1 output
__device__ float g_p2[512 * 64 * 12 * 12];     // pool2 output (fc1 input)
__device__ float g_part[16 * 512 * 128];       // fc1 split-K partials
__device__ float g_h[512 * 128];               // fc1 relu output

__device__ __forceinline__ float tf32_rna(float v) {
    uint32_t u;
    asm("cvt.rna.tf32.f32 %0, %1;" : "=r"(u) : "f"(v));
    return __uint_as_float(u);
}

// m16n8k8 tf32 mma, row.col, fp32 accumulate (sm_80+ baseline PTX)
__device__ __forceinline__ void mma_tf32(float* c,
                                         float a0, float a1, float a2, float a3,
                                         float b0, float b1)
{
    asm volatile(
        "mma.sync.aligned.m16n8k8.row.col.f32.tf32.tf32.f32 "
        "{%0,%1,%2,%3}, {%4,%5,%6,%7}, {%8,%9}, {%0,%1,%2,%3};"
        : "+f"(c[0]), "+f"(c[1]), "+f"(c[2]), "+f"(c[3])
        : "r"(__float_as_uint(a0)), "r"(__float_as_uint(a1)),
          "r"(__float_as_uint(a2)), "r"(__float_as_uint(a3)),
          "r"(__float_as_uint(b0)), "r"(__float_as_uint(b1)));
}

// ---------------------------------------------------------------------------
// Kernel 1: conv1 + ReLU + maxpool (fp32) — R9 version
// ---------------------------------------------------------------------------
__global__ void __launch_bounds__(256) k_conv1(const float* __restrict__ x,
                                               const float* __restrict__ w,
                                               const float* __restrict__ bias)
{
    __shared__ float s_x[54 * 55];
    __shared__ float s_w[32 * 9];
    __shared__ float s_b[32];

    const int bb = blockIdx.x;
    const float* xb = x + bb * 54 * 54;
    for (int i = threadIdx.x; i < 54 * 54; i += 256) {
        int y = i / 54, c = i - y * 54;
        s_x[y * 55 + c] = xb[i];
    }
    for (int i = threadIdx.x; i < 32 * 9; i += 256) s_w[i] = w[i];
    if (threadIdx.x < 32) s_b[threadIdx.x] = bias[threadIdx.x];
    __syncthreads();

    float* outb = g_p1 + bb * 32 * 676;
    for (int oc = 0; oc < 32; oc++) {
        float wr[9];
#pragma unroll
        for (int i = 0; i < 9; i++) wr[i] = s_w[oc * 9 + i];
        const float bv = s_b[oc];
        for (int pos = threadIdx.x; pos < 676; pos += 256) {
            const int py = pos / 26, px = pos - py * 26;
            const int Y0 = py * 2, X0 = px * 2;
            float in[4][4];
#pragma unroll
            for (int dy = 0; dy < 4; dy++)
#pragma unroll
                for (int dx = 0; dx < 4; dx++)
                    in[dy][dx] = s_x[(Y0 + dy) * 55 + X0 + dx];
            float m = 0.0f;
#pragma unroll
            for (int dy = 0; dy < 2; dy++)
#pragma unroll
                for (int dx = 0; dx < 2; dx++) {
                    float acc = bv;
#pragma unroll
                    for (int ky = 0; ky < 3; ky++)
#pragma unroll
                        for (int kx = 0; kx < 3; kx++)
                            acc = fmaf(wr[ky * 3 + kx], in[dy + ky][dx + kx], acc);
                    m = fmaxf(m, acc);
                }
            outb[oc * 676 + pos] = m;
        }
    }
}

// ---------------------------------------------------------------------------
// Kernel 2: conv2 via mma.sync tf32 implicit-im2col + ReLU + maxpool.
// 576 threads / 18 warps (was 288/9): warp owns 2 m-tiles x 8 n-tiles.
// 4.5 warps/SMSP for latency hiding of the LDS->mma chains.
// D[576 pos x 64 oc] = A[576 x 288] * B[288 x 64], A gathered from X planes.
// ---------------------------------------------------------------------------
#define C2_XS     21632
#define C2_BS     20736
#define C2_SMEMF  (C2_XS + C2_BS + 288)          // 42656 floats
#define C2_DSMEM  (C2_SMEMF * 4)                 // 170624 bytes

__global__ void __launch_bounds__(576, 1) k_conv2(const float* __restrict__ w,
                                                  const float* __restrict__ bias)
{
    extern __shared__ float sm[];
    float* Xs  = sm;                 // 32 planes of 26x26
    float* Bsm = sm + C2_XS;         // [288][72]
    int*   offs = (int*)(sm + C2_XS + C2_BS);    // [288]
    __shared__ float s_b[64];

    const int tid = threadIdx.x;
    const int wid = tid >> 5, lane = tid & 31;
    const int grp = lane >> 2, qid = lane & 3;
    const int bb = blockIdx.x;

    // ---- prologue ----
    if (tid < 288) {
        const int ic = tid / 9, r = tid - ic * 9;
        offs[tid] = ic * 676 + (r / 3) * 26 + (r % 3);
    }
    if (tid >= 288 && tid < 352) s_b[tid - 288] = bias[tid - 288];

    if (tid < 64) {
        // B: thread owns one oc row, streams k; STS conflict-free per k.
        const int oc = tid;
        const float* wr = w + oc * 288;
#pragma unroll 4
        for (int k = 0; k < 288; k += 4) {
            const float4 v = *(const float4*)(wr + k);
            Bsm[(k + 0) * 72 + oc] = tf32_rna(v.x);
            Bsm[(k + 1) * 72 + oc] = tf32_rna(v.y);
            Bsm[(k + 2) * 72 + oc] = tf32_rna(v.z);
            Bsm[(k + 3) * 72 + oc] = tf32_rna(v.w);
        }
    } else {
        // X: 512 threads, float4 loads (21632 = 5408 float4s)
        const float4* src = (const float4*)(g_p1 + bb * C2_XS);
        for (int i = tid - 64; i < C2_XS / 4; i += 512) {
            const float4 v = src[i];
            float* d = Xs + i * 4;
            d[0] = tf32_rna(v.x); d[1] = tf32_rna(v.y);
            d[2] = tf32_rna(v.z); d[3] = tf32_rna(v.w);
        }
    }
    __syncthreads();

    // warp w -> m-tiles {2w, 2w+1}; per-thread row offsets
    int poA[2], poB[2];
#pragma unroll
    for (int mt = 0; mt < 2; mt++) {
        const int rA = (wid * 2 + mt) * 16 + grp;
        const int yA = rA / 24, xA = rA - yA * 24;
        poA[mt] = yA * 26 + xA;
        const int rB = rA + 8;
        const int yB = rB / 24, xB = rB - yB * 24;
        poB[mt] = yB * 26 + xB;
    }

    float c[2][8][4];
#pragma unroll
    for (int mt = 0; mt < 2; mt++)
#pragma unroll
        for (int nt = 0; nt < 8; nt++)
#pragma unroll
            for (int j = 0; j < 4; j++) c[mt][nt][j] = 0.0f;

    // ---- mainloop: 36 k-steps of 8 ----
    for (int ks = 0; ks < 36; ks++) {
        const int klo = ks * 8 + qid;
        const int offlo = offs[klo];
        const int offhi = offs[klo + 4];

        // B fragments: conflict-free (bank = qid*8 + grp)
        const float* bl = Bsm + klo * 72 + grp;
        float bq[8][2];
#pragma unroll
        for (int nt = 0; nt < 8; nt++) {
            bq[nt][0] = bl[nt * 8];
            bq[nt][1] = bl[4 * 72 + nt * 8];
        }

#pragma unroll
        for (int mt = 0; mt < 2; mt++) {
            const float a0 = Xs[offlo + poA[mt]];
            const float a1 = Xs[offlo + poB[mt]];
            const float a2 = Xs[offhi + poA[mt]];
            const float a3 = Xs[offhi + poB[mt]];
#pragma unroll
            for (int nt = 0; nt < 8; nt++)
                mma_tf32(c[mt][nt], a0, a1, a2, a3, bq[nt][0], bq[nt][1]);
        }
    }

    __syncthreads();   // all smem reads done before cb overwrite

    // ---- epilogue: bias + relu into cb[pos][66], then 2x2 maxpool ----
    float* cb = sm;    // [576][66] = 38016 floats < 42656
#pragma unroll
    for (int mt = 0; mt < 2; mt++) {
        const int row = (wid * 2 + mt) * 16 + grp;
#pragma unroll
        for (int nt = 0; nt < 8; nt++) {
            const int col = nt * 8 + qid * 2;
            const float b0 = s_b[col], b1 = s_b[col + 1];
            cb[row * 66 + col]           = fmaxf(c[mt][nt][0] + b0, 0.0f);
            cb[row * 66 + col + 1]       = fmaxf(c[mt][nt][1] + b1, 0.0f);
            cb[(row + 8) * 66 + col]     = fmaxf(c[mt][nt][2] + b0, 0.0f);
            cb[(row + 8) * 66 + col + 1] = fmaxf(c[mt][nt][3] + b1, 0.0f);
        }
    }
    __syncthreads();

    float* outb = g_p2 + bb * 9216;
    for (int i = tid; i < 9216; i += 576) {
        const int oc = i / 144, r = i - oc * 144;
        const int py = r / 12, px = r - py * 12;
        const int p0 = (2 * py) * 24 + 2 * px;
        const float v0 = cb[p0 * 66 + oc];
        const float v1 = cb[(p0 + 1) * 66 + oc];
        const float v2 = cb[(p0 + 24) * 66 + oc];
        const float v3 = cb[(p0 + 25) * 66 + oc];
        outb[i] = fmaxf(fmaxf(v0, v1), fmaxf(v2, v3));
    }
}

// ---------------------------------------------------------------------------
// Kernel 3: fc1 GEMM, split-K (fp32) — R9 version
// ---------------------------------------------------------------------------
__global__ void __launch_bounds__(256) k_fc1(const float* __restrict__ W)
{
    __shared__ float As[64][17];
    __shared__ float Bs[128][17];

    const int mb = blockIdx.x;
    const int sp = blockIdx.y;
    const int tid = threadIdx.x;
    const float* Ab = g_p2 + (mb * 64) * 9216;
    const int k0 = sp * 576;

    float acc[4][8];
#pragma unroll
    for (int i = 0; i < 4; i++)
#pragma unroll
        for (int j = 0; j < 8; j++) acc[i][j] = 0.0f;

    const int tm = tid >> 4, tn = tid & 15;
    const int lr = tid >> 2;
    const int lc = (tid & 3) * 4;

    for (int ks = 0; ks < 576; ks += 16) {
        {
            const float4 v = *(const float4*)(Ab + lr * 9216 + k0 + ks + lc);
            As[lr][lc + 0] = v.x; As[lr][lc + 1] = v.y;
            As[lr][lc + 2] = v.z; As[lr][lc + 3] = v.w;
#pragma unroll
            for (int g = 0; g < 2; g++) {
                const int rr = lr + 64 * g;
                const float4 u = *(const float4*)(W + rr * 9216 + k0 + ks + lc);
                Bs[rr][lc + 0] = u.x; Bs[rr][lc + 1] = u.y;
                Bs[rr][lc + 2] = u.z; Bs[rr][lc + 3] = u.w;
            }
        }
        __syncthreads();
#pragma unroll
        for (int kk = 0; kk < 16; kk++) {
            float a[4], bv[8];
#pragma unroll
            for (int i = 0; i < 4; i++) a[i] = As[tm * 4 + i][kk];
#pragma unroll
            for (int j = 0; j < 8; j++) bv[j] = Bs[tn * 8 + j][kk];
#pragma unroll
            for (int i = 0; i < 4; i++)
#pragma unroll
                for (int j = 0; j < 8; j++)
                    acc[i][j] = fmaf(a[i], bv[j], acc[i][j]);
        }
        __syncthreads();
    }

    float* out = g_part + sp * (512 * 128) + (mb * 64) * 128;
#pragma unroll
    for (int i = 0; i < 4; i++)
#pragma unroll
        for (int j = 0; j < 8; j++)
            out[(tm * 4 + i) * 128 + tn * 8 + j] = acc[i][j];
}

// ---------------------------------------------------------------------------
// Kernel 4: reduce split-K partials + bias + ReLU
// ---------------------------------------------------------------------------
__global__ void k_fc1red(const float* __restrict__ b1)
{
    const int idx = blockIdx.x * blockDim.x + threadIdx.x;
    const int n = idx & 127;
    float s = b1[n];
#pragma unroll
    for (int sp = 0; sp < 16; sp++) s += g_part[sp * 65536 + idx];
    g_h[idx] = fmaxf(s, 0.0f);
}

// ---------------------------------------------------------------------------
// Kernel 5: fc2 (128 -> 10)
// ---------------------------------------------------------------------------
__global__ void __launch_bounds__(128) k_fc2(const float* __restrict__ W2,
                                             const float* __restrict__ b2,
                                             float* __restrict__ out)
{
    __shared__ float sh[128];
    const int bb = blockIdx.x;
    const int tid = threadIdx.x;
    sh[tid] = g_h[bb * 128 + tid];
    __syncthreads();
    const int warp = tid >> 5, lane = tid & 31;
    for (int o = warp; o < 10; o += 4) {
        float s = 0.0f;
#pragma unroll
        for (int i = 0; i < 4; i++)
            s = fmaf(sh[lane + 32 * i], W2[o * 128 + lane + 32 * i], s);
#pragma unroll
        for (int off = 16; off > 0; off >>= 1)
            s += __shfl_down_sync(0xffffffffu, s, off);
        if (lane == 0) out[bb * 10 + o] = s + b2[o];
    }
}

// ---------------------------------------------------------------------------
extern "C" void kernel_launch(void* const* d_in, const int* in_sizes, int n_in,
                              void* d_out, int out_size)
{
    const float* x   = (const float*)d_in[0];
    const float* c1w = (const float*)d_in[1];
    const float* c1b = (const float*)d_in[2];
    const float* c2w = (const float*)d_in[3];
    const float* c2b = (const float*)d_in[4];
    const float* f1w = (const float*)d_in[5];
    const float* f1b = (const float*)d_in[6];
    const float* f2w = (const float*)d_in[7];
    const float* f2b = (const float*)d_in[8];
    float* out = (float*)d_out;

    cudaFuncSetAttribute(k_conv2, cudaFuncAttributeMaxDynamicSharedMemorySize,
                         C2_DSMEM);

    k_conv1<<<512, 256>>>(x, c1w, c1b);
    k_conv2<<<512, 576, C2_DSMEM>>>(c2w, c2b);
    dim3 g3(8, 16);
    k_fc1<<<g3, 256>>>(f1w);
    k_fc1red<<<256, 256>>>(f1b);
    k_fc2<<<512, 128>>>(f2w, f2b, out);
}

// round 17
// speedup vs baseline: 1.2009x; 1.0997x over previous
#include <cuda_runtime.h>
#include <cuda_fp16.h>
#include <cstdint>

// ---------------------------------------------------------------------------
// LNSNet: conv1(1->32,3x3)+relu+pool2 -> conv2(32->64,3x3)+relu+pool2 (mma f16)
//         -> fc1(9216->128)+relu -> fc2(128->10).  Batch 512.
// ---------------------------------------------------------------------------

__device__ float g_p1[512 * 32 * 26 * 26];     // pool1 output
__device__ float g_p2[512 * 64 * 12 * 12];     // pool2 output (fc1 input)
__device__ float g_part[16 * 512 * 128];       // fc1 split-K partials
__device__ float g_h[512 * 128];               // fc1 relu output

__device__ __forceinline__ uint32_t pack_h2(__half a, __half b) {
    __half2 h = __halves2half2(a, b);
    return *reinterpret_cast<uint32_t*>(&h);
}

// m16n8k16 fp16 mma, row.col, fp32 accumulate (sm_80+ baseline PTX)
__device__ __forceinline__ void mma_f16(float* c,
                                        uint32_t a0, uint32_t a1,
                                        uint32_t a2, uint32_t a3,
                                        uint32_t b0, uint32_t b1)
{
    asm volatile(
        "mma.sync.aligned.m16n8k16.row.col.f32.f16.f16.f32 "
        "{%0,%1,%2,%3}, {%4,%5,%6,%7}, {%8,%9}, {%0,%1,%2,%3};"
        : "+f"(c[0]), "+f"(c[1]), "+f"(c[2]), "+f"(c[3])
        : "r"(a0), "r"(a1), "r"(a2), "r"(a3), "r"(b0), "r"(b1));
}

// ---------------------------------------------------------------------------
// Kernel 1: conv1 + ReLU + maxpool (fp32) — R9 version
// ---------------------------------------------------------------------------
__global__ void __launch_bounds__(256) k_conv1(const float* __restrict__ x,
                                               const float* __restrict__ w,
                                               const float* __restrict__ bias)
{
    __shared__ float s_x[54 * 55];
    __shared__ float s_w[32 * 9];
    __shared__ float s_b[32];

    const int bb = blockIdx.x;
    const float* xb = x + bb * 54 * 54;
    for (int i = threadIdx.x; i < 54 * 54; i += 256) {
        int y = i / 54, c = i - y * 54;
        s_x[y * 55 + c] = xb[i];
    }
    for (int i = threadIdx.x; i < 32 * 9; i += 256) s_w[i] = w[i];
    if (threadIdx.x < 32) s_b[threadIdx.x] = bias[threadIdx.x];
    __syncthreads();

    float* outb = g_p1 + bb * 32 * 676;
    for (int oc = 0; oc < 32; oc++) {
        float wr[9];
#pragma unroll
        for (int i = 0; i < 9; i++) wr[i] = s_w[oc * 9 + i];
        const float bv = s_b[oc];
        for (int pos = threadIdx.x; pos < 676; pos += 256) {
            const int py = pos / 26, px = pos - py * 26;
            const int Y0 = py * 2, X0 = px * 2;
            float in[4][4];
#pragma unroll
            for (int dy = 0; dy < 4; dy++)
#pragma unroll
                for (int dx = 0; dx < 4; dx++)
                    in[dy][dx] = s_x[(Y0 + dy) * 55 + X0 + dx];
            float m = 0.0f;
#pragma unroll
            for (int dy = 0; dy < 2; dy++)
#pragma unroll
                for (int dx = 0; dx < 2; dx++) {
                    float acc = bv;
#pragma unroll
                    for (int ky = 0; ky < 3; ky++)
#pragma unroll
                        for (int kx = 0; kx < 3; kx++)
                            acc = fmaf(wr[ky * 3 + kx], in[dy + ky][dx + kx], acc);
                    m = fmaxf(m, acc);
                }
            outb[oc * 676 + pos] = m;
        }
    }
}

// ---------------------------------------------------------------------------
// Kernel 2: conv2 via mma.sync m16n8k16 fp16 implicit-im2col + ReLU + maxpool.
// 576 threads / 18 warps; warp owns 2 m-tiles x 8 n-tiles.
// D[576 pos x 64 oc] = A[576 x 288] * B[288 x 64] (fp32 accumulate).
// Dyn smem (bytes):
//   [0,      43264)  Xh: 32 planes 26x26 fp16
//   [43264,  84736)  Bh2: half2[144][72]  (k-pairs x oc, pad 72)
//   [84736,  85888)  offs: int[288]
//   epilogue reuses [0, 152064) as conv buffer cb[576][66] fp32
// ---------------------------------------------------------------------------
#define C2_XH_BYTES  43264
#define C2_B_BYTES   41472
#define C2_DSMEM     152064

__global__ void __launch_bounds__(576, 1) k_conv2(const float* __restrict__ w,
                                                  const float* __restrict__ bias)
{
    extern __shared__ char dsm[];
    __half*  Xh   = (__half*)dsm;                              // [21632]
    __half2* Bh2  = (__half2*)(dsm + C2_XH_BYTES);             // [144*72]
    int*     offs = (int*)(dsm + C2_XH_BYTES + C2_B_BYTES);    // [288]
    __shared__ float s_b[64];

    const int tid = threadIdx.x;
    const int wid = tid >> 5, lane = tid & 31;
    const int grp = lane >> 2, qid = lane & 3;
    const int bb = blockIdx.x;

    // ---- prologue ----
    if (tid < 288) {
        const int ic = tid / 9, r = tid - ic * 9;
        offs[tid] = ic * 676 + (r / 3) * 26 + (r % 3);
    }
    if (tid >= 288 && tid < 352) s_b[tid - 288] = bias[tid - 288];

    if (tid < 64) {
        // B: thread owns one oc column; packs k-pairs. STS conflict-free.
        const int oc = tid;
        const float* wr = w + oc * 288;
#pragma unroll 4
        for (int k = 0; k < 288; k += 4) {
            const float4 v = *(const float4*)(wr + k);
            Bh2[(k >> 1) * 72 + oc]       = __floats2half2_rn(v.x, v.y);
            Bh2[((k >> 1) + 1) * 72 + oc] = __floats2half2_rn(v.z, v.w);
        }
    } else {
        // X: 512 threads, float4 -> 2x half2 (21632 floats = 5408 float4)
        const float4* src = (const float4*)(g_p1 + bb * 21632);
        for (int i = tid - 64; i < 5408; i += 512) {
            const float4 v = src[i];
            __half2* d = (__half2*)(Xh + i * 4);
            d[0] = __floats2half2_rn(v.x, v.y);
            d[1] = __floats2half2_rn(v.z, v.w);
        }
    }
    __syncthreads();

    // warp w -> m-tiles {2w, 2w+1}; per-thread row offsets
    int poA[2], poB[2];
#pragma unroll
    for (int mt = 0; mt < 2; mt++) {
        const int rA = (wid * 2 + mt) * 16 + grp;
        const int yA = rA / 24, xA = rA - yA * 24;
        poA[mt] = yA * 26 + xA;
        const int rB = rA + 8;
        const int yB = rB / 24, xB = rB - yB * 24;
        poB[mt] = yB * 26 + xB;
    }

    float c[2][8][4];
#pragma unroll
    for (int mt = 0; mt < 2; mt++)
#pragma unroll
        for (int nt = 0; nt < 8; nt++)
#pragma unroll
            for (int j = 0; j < 4; j++) c[mt][nt][j] = 0.0f;

    // ---- mainloop: 18 k-steps of 16 ----
    for (int ks = 0; ks < 18; ks++) {
        const int kb = ks * 16 + 2 * qid;
        const int o0 = offs[kb],     o1 = offs[kb + 1];
        const int o2 = offs[kb + 8], o3 = offs[kb + 9];

        // B fragments: bank = 8*qid + grp -> conflict-free
        const __half2* bl = Bh2 + (ks * 8 + qid) * 72 + grp;
        uint32_t bq[8][2];
#pragma unroll
        for (int nt = 0; nt < 8; nt++) {
            bq[nt][0] = *(const uint32_t*)(bl + nt * 8);
            bq[nt][1] = *(const uint32_t*)(bl + 288 + nt * 8);   // k2 + 4
        }

#pragma unroll
        for (int mt = 0; mt < 2; mt++) {
            const uint32_t a0 = pack_h2(Xh[o0 + poA[mt]], Xh[o1 + poA[mt]]);
            const uint32_t a1 = pack_h2(Xh[o0 + poB[mt]], Xh[o1 + poB[mt]]);
            const uint32_t a2 = pack_h2(Xh[o2 + poA[mt]], Xh[o3 + poA[mt]]);
            const uint32_t a3 = pack_h2(Xh[o2 + poB[mt]], Xh[o3 + poB[mt]]);
#pragma unroll
            for (int nt = 0; nt < 8; nt++)
                mma_f16(c[mt][nt], a0, a1, a2, a3, bq[nt][0], bq[nt][1]);
        }
    }

    __syncthreads();   // all smem reads done before cb overwrite

    // ---- epilogue: bias + relu into cb[pos][66], then 2x2 maxpool ----
    float* cb = (float*)dsm;    // [576][66] = 152064 B
#pragma unroll
    for (int mt = 0; mt < 2; mt++) {
        const int row = (wid * 2 + mt) * 16 + grp;
#pragma unroll
        for (int nt = 0; nt < 8; nt++) {
            const int col = nt * 8 + qid * 2;
            const float b0 = s_b[col], b1 = s_b[col + 1];
            cb[row * 66 + col]           = fmaxf(c[mt][nt][0] + b0, 0.0f);
            cb[row * 66 + col + 1]       = fmaxf(c[mt][nt][1] + b1, 0.0f);
            cb[(row + 8) * 66 + col]     = fmaxf(c[mt][nt][2] + b0, 0.0f);
            cb[(row + 8) * 66 + col + 1] = fmaxf(c[mt][nt][3] + b1, 0.0f);
        }
    }
    __syncthreads();

    float* outb = g_p2 + bb * 9216;
    for (int i = tid; i < 9216; i += 576) {
        const int oc = i / 144, r = i - oc * 144;
        const int py = r / 12, px = r - py * 12;
        const int p0 = (2 * py) * 24 + 2 * px;
        const float v0 = cb[p0 * 66 + oc];
        const float v1 = cb[(p0 + 1) * 66 + oc];
        const float v2 = cb[(p0 + 24) * 66 + oc];
        const float v3 = cb[(p0 + 25) * 66 + oc];
        outb[i] = fmaxf(fmaxf(v0, v1), fmaxf(v2, v3));
    }
}

// ---------------------------------------------------------------------------
// Kernel 3: fc1 GEMM, split-K (fp32) — R9 version
// ---------------------------------------------------------------------------
__global__ void __launch_bounds__(256) k_fc1(const float* __restrict__ W)
{
    __shared__ float As[64][17];
    __shared__ float Bs[128][17];

    const int mb = blockIdx.x;
    const int sp = blockIdx.y;
    const int tid = threadIdx.x;
    const float* Ab = g_p2 + (mb * 64) * 9216;
    const int k0 = sp * 576;

    float acc[4][8];
#pragma unroll
    for (int i = 0; i < 4; i++)
#pragma unroll
        for (int j = 0; j < 8; j++) acc[i][j] = 0.0f;

    const int tm = tid >> 4, tn = tid & 15;
    const int lr = tid >> 2;
    const int lc = (tid & 3) * 4;

    for (int ks = 0; ks < 576; ks += 16) {
        {
            const float4 v = *(const float4*)(Ab + lr * 9216 + k0 + ks + lc);
            As[lr][lc + 0] = v.x; As[lr][lc + 1] = v.y;
            As[lr][lc + 2] = v.z; As[lr][lc + 3] = v.w;
#pragma unroll
            for (int g = 0; g < 2; g++) {
                const int rr = lr + 64 * g;
                const float4 u = *(const float4*)(W + rr * 9216 + k0 + ks + lc);
                Bs[rr][lc + 0] = u.x; Bs[rr][lc + 1] = u.y;
                Bs[rr][lc + 2] = u.z; Bs[rr][lc + 3] = u.w;
            }
        }
        __syncthreads();
#pragma unroll
        for (int kk = 0; kk < 16; kk++) {
            float a[4], bv[8];
#pragma unroll
            for (int i = 0; i < 4; i++) a[i] = As[tm * 4 + i][kk];
#pragma unroll
            for (int j = 0; j < 8; j++) bv[j] = Bs[tn * 8 + j][kk];
#pragma unroll
            for (int i = 0; i < 4; i++)
#pragma unroll
                for (int j = 0; j < 8; j++)
                    acc[i][j] = fmaf(a[i], bv[j], acc[i][j]);
        }
        __syncthreads();
    }

    float* out = g_part + sp * (512 * 128) + (mb * 64) * 128;
#pragma unroll
    for (int i = 0; i < 4; i++)
#pragma unroll
        for (int j = 0; j < 8; j++)
            out[(tm * 4 + i) * 128 + tn * 8 + j] = acc[i][j];
}

// ---------------------------------------------------------------------------
// Kernel 4: reduce split-K partials + bias + ReLU
// ---------------------------------------------------------------------------
__global__ void k_fc1red(const float* __restrict__ b1)
{
    const int idx = blockIdx.x * blockDim.x + threadIdx.x;
    const int n = idx & 127;
    float s = b1[n];
#pragma unroll
    for (int sp = 0; sp < 16; sp++) s += g_part[sp * 65536 + idx];
    g_h[idx] = fmaxf(s, 0.0f);
}

// ---------------------------------------------------------------------------
// Kernel 5: fc2 (128 -> 10)
// ---------------------------------------------------------------------------
__global__ void __launch_bounds__(128) k_fc2(const float* __restrict__ W2,
                                             const float* __restrict__ b2,
                                             float* __restrict__ out)
{
    __shared__ float sh[128];
    const int bb = blockIdx.x;
    const int tid = threadIdx.x;
    sh[tid] = g_h[bb * 128 + tid];
    __syncthreads();
    const int warp = tid >> 5, lane = tid & 31;
    for (int o = warp; o < 10; o += 4) {
        float s = 0.0f;
#pragma unroll
        for (int i = 0; i < 4; i++)
            s = fmaf(sh[lane + 32 * i], W2[o * 128 + lane + 32 * i], s);
#pragma unroll
        for (int off = 16; off > 0; off >>= 1)
            s += __shfl_down_sync(0xffffffffu, s, off);
        if (lane == 0) out[bb * 10 + o] = s + b2[o];
    }
}

// ---------------------------------------------------------------------------
extern "C" void kernel_launch(void* const* d_in, const int* in_sizes, int n_in,
                              void* d_out, int out_size)
{
    const float* x   = (const float*)d_in[0];
    const float* c1w = (const float*)d_in[1];
    const float* c1b = (const float*)d_in[2];
    const float* c2w = (const float*)d_in[3];
    const float* c2b = (const float*)d_in[4];
    const float* f1w = (const float*)d_in[5];
    const float* f1b = (const float*)d_in[6];
    const float* f2w = (const float*)d_in[7];
    const float* f2b = (const float*)d_in[8];
    float* out = (float*)d_out;

    cudaFuncSetAttribute(k_conv2, cudaFuncAttributeMaxDynamicSharedMemorySize,
                         C2_DSMEM);

    k_conv1<<<512, 256>>>(x, c1w, c1b);
    k_conv2<<<512, 576, C2_DSMEM>>>(c2w, c2b);
    dim3 g3(8, 16);
    k_fc1<<<g3, 256>>>(f1w);
    k_fc1red<<<256, 256>>>(f1b);
    k_fc2<<<512, 128>>>(f2w, f2b, out);
}